// round 3
// baseline (speedup 1.0000x reference)
#include <cuda_runtime.h>

// ---------------------------------------------------------------------------
// VectorQuantizer forward, fused.  N=8192 tokens x V=8192 codes x C=32.
// Forward-value collapses:
//   logits == S == zfn @ en^T ; argmin d == argmin_v (esq_v - 2 S[n,v])
//   z_q == en[idx] ; out == z_q (straight-through)
//   commit = BETA * mean_n( log(sum_v exp(S[n,v])) - S[n,idx_n] )
//   vq     = mean (en[idx]-zfn)^2
// dot in [-1,1] (normalized operands) -> no-max logsumexp is safe.
// Scale by log2e folded into esq so EX2 needs no per-element rescale; argmin
// ordering preserved (positive scale).
// ---------------------------------------------------------------------------

#define N_TOK 8192
#define V_CODES 8192
#define C_DIM 32
#define VS 16
#define VPB (V_CODES / VS)      // 512 codes per block
#define TILE_V 64
#define TPB 256
#define TOKB 512                // 2 tokens per thread
#define L2EPS 1e-12f
#define L2E 1.4426950408889634f
#define LN2 0.6931471805599453f

typedef unsigned long long u64;
typedef unsigned int u32;

// ------------------------- device scratch ----------------------------------
__device__ float g_en[V_CODES * C_DIM];     // l2-normalized codebook
__device__ u64   g_esqp[V_CODES];           // (esq*log2e, esq*log2e) packed
__device__ float g_zfn[N_TOK * C_DIM];      // l2-normalized tokens
__device__ float g_pd[N_TOK * VS];          // partial best (scaled) distance
__device__ int   g_pi[N_TOK * VS];          // partial best index
__device__ float g_ps[N_TOK * VS];          // partial exp-sum
__device__ float g_blk[64][2];              // per-block loss partials
__device__ int   g_cnt;                     // combine completion counter

// ------------------------- packed f32x2 helpers ----------------------------
__device__ __forceinline__ void fma2(u64& d, u64 a, u64 b) {
    asm("fma.rn.f32x2 %0, %1, %2, %0;" : "+l"(d) : "l"(a), "l"(b));
}
__device__ __forceinline__ u64 fma2c(u64 a, u64 b, u64 c) {
    u64 r; asm("fma.rn.f32x2 %0, %1, %2, %3;" : "=l"(r) : "l"(a), "l"(b), "l"(c));
    return r;
}
__device__ __forceinline__ u64 mul2(u64 a, u64 b) {
    u64 r; asm("mul.rn.f32x2 %0, %1, %2;" : "=l"(r) : "l"(a), "l"(b));
    return r;
}
__device__ __forceinline__ u64 add2(u64 a, u64 b) {
    u64 r; asm("add.rn.f32x2 %0, %1, %2;" : "=l"(r) : "l"(a), "l"(b));
    return r;
}
__device__ __forceinline__ u64 pack2(u32 lo, u32 hi) {
    u64 r; asm("mov.b64 %0, {%1,%2};" : "=l"(r) : "r"(lo), "r"(hi));
    return r;
}
__device__ __forceinline__ void unpack2(u64 v, u32& lo, u32& hi) {
    asm("mov.b64 {%0,%1}, %2;" : "=r"(lo), "=r"(hi) : "l"(v));
}
__device__ __forceinline__ float ex2f(float x) {
    float r; asm("ex2.approx.f32 %0, %1;" : "=f"(r) : "f"(x));
    return r;
}
__device__ __forceinline__ float lg2f(float x) {
    float r; asm("lg2.approx.f32 %0, %1;" : "=f"(r) : "f"(x));
    return r;
}

// ------------------------- kernel 1: prep (emb + z) ------------------------
__global__ void prep(const float* __restrict__ z, const float* __restrict__ emb) {
    int tid = threadIdx.x;
    if (blockIdx.x < 32) {
        int r = blockIdx.x * 256 + tid;
        const float4* src = (const float4*)(emb + r * C_DIM);
        float4 v[8];
        float ss = 0.f;
#pragma unroll
        for (int i = 0; i < 8; i++) {
            v[i] = src[i];
            ss += v[i].x * v[i].x + v[i].y * v[i].y + v[i].z * v[i].z + v[i].w * v[i].w;
        }
        float rcp = 1.0f / fmaxf(sqrtf(ss), L2EPS);
        float es = 0.f;
        float4* dst = (float4*)(g_en + r * C_DIM);
#pragma unroll
        for (int i = 0; i < 8; i++) {
            v[i].x *= rcp; v[i].y *= rcp; v[i].z *= rcp; v[i].w *= rcp;
            es += v[i].x * v[i].x + v[i].y * v[i].y + v[i].z * v[i].z + v[i].w * v[i].w;
            dst[i] = v[i];
        }
        u32 eb = __float_as_uint(es * L2E);
        g_esqp[r] = pack2(eb, eb);
    } else {
        int n = (blockIdx.x - 32) * 256 + tid;
        int b = n >> 10, hw = n & 1023;
        const float* zp = z + b * (C_DIM * 1024) + hw;
        float val[C_DIM];
        float ss = 0.f;
#pragma unroll
        for (int c = 0; c < C_DIM; c++) {
            val[c] = zp[c * 1024];
            ss += val[c] * val[c];
        }
        float rcp = 1.0f / fmaxf(sqrtf(ss), L2EPS);
        float4* dst = (float4*)(g_zfn + n * C_DIM);
#pragma unroll
        for (int i = 0; i < 8; i++) {
            dst[i] = make_float4(val[4 * i] * rcp, val[4 * i + 1] * rcp,
                                 val[4 * i + 2] * rcp, val[4 * i + 3] * rcp);
        }
    }
}

// ------------------------- kernel 2: fused similarity scan -----------------
// grid = (16, VS). Block: 512 tokens (2/thread) x 512 codes.
__global__ __launch_bounds__(TPB, 2) void vq_main() {
    __shared__ float sc[TILE_V * C_DIM];
    __shared__ u64 ssqp[TILE_V];
    int tid = threadIdx.x;
    int tok0 = blockIdx.x * TOKB + tid;
    int tok1 = tok0 + TPB;
    int vbase = blockIdx.y * VPB;

    u64 zz0[16], zz1[16];
    {
        const u64* p0 = (const u64*)(g_zfn + tok0 * C_DIM);
        const u64* p1 = (const u64*)(g_zfn + tok1 * C_DIM);
#pragma unroll
        for (int k = 0; k < 16; k++) { zz0[k] = p0[k]; zz1[k] = p1[k]; }
    }

    const u32 l2eb = __float_as_uint(L2E);
    const u32 n2b  = __float_as_uint(-2.0f);
    const u64 PL2E = pack2(l2eb, l2eb);
    const u64 PN2  = pack2(n2b, n2b);

    float bestd0 = 3.4e38f, bestd1 = 3.4e38f;
    int bi0 = 0, bi1 = 0;
    float s0 = 0.f, s1 = 0.f;

    for (int t = 0; t < VPB / TILE_V; t++) {
        int v0 = vbase + t * TILE_V;
        {
            const float4* src = (const float4*)(g_en + v0 * C_DIM);
            float4* dst = (float4*)sc;
            dst[tid] = src[tid];
            dst[tid + TPB] = src[tid + TPB];
            if (tid < TILE_V) ssqp[tid] = g_esqp[v0 + tid];
        }
        __syncthreads();

#pragma unroll 4
        for (int v = 0; v < TILE_V; v++) {
            const ulonglong2* e = (const ulonglong2*)(sc + v * C_DIM);
            ulonglong2 ev[8];
#pragma unroll
            for (int k = 0; k < 8; k++) ev[k] = e[k];   // 8x LDS.128 broadcast

            u64 a00 = mul2(zz0[0], ev[0].x);
            u64 a01 = mul2(zz0[1], ev[0].y);
            u64 a10 = mul2(zz1[0], ev[0].x);
            u64 a11 = mul2(zz1[1], ev[0].y);
#pragma unroll
            for (int k = 1; k < 8; k++) {
                fma2(a00, zz0[2 * k],     ev[k].x);
                fma2(a01, zz0[2 * k + 1], ev[k].y);
                fma2(a10, zz1[2 * k],     ev[k].x);
                fma2(a11, zz1[2 * k + 1], ev[k].y);
            }
            u64 r0 = add2(a00, a01);
            u64 r1 = add2(a10, a11);
            u32 r0l, r0h, r1l, r1h;
            unpack2(r0, r0l, r0h);
            unpack2(r1, r1l, r1h);
            u64 dd = add2(pack2(r0l, r1l), pack2(r0h, r1h)); // (dot0, dot1)
            u64 uu = mul2(dd, PL2E);                         // log2e * dot
            u64 dv = fma2c(uu, PN2, ssqp[v]);                // (d0, d1), scaled dist
            u32 d0b, d1b, u0b, u1b;
            unpack2(dv, d0b, d1b);
            unpack2(uu, u0b, u1b);
            float d0 = __uint_as_float(d0b), d1 = __uint_as_float(d1b);
            if (d0 < bestd0) { bestd0 = d0; bi0 = v0 + v; }
            if (d1 < bestd1) { bestd1 = d1; bi1 = v0 + v; }
            s0 += ex2f(__uint_as_float(u0b));   // exp(dot), no overflow: dot<=1
            s1 += ex2f(__uint_as_float(u1b));
        }
        __syncthreads();
    }

    int o0 = tok0 * VS + blockIdx.y;
    int o1 = tok1 * VS + blockIdx.y;
    g_pd[o0] = bestd0; g_pi[o0] = bi0; g_ps[o0] = s0;
    g_pd[o1] = bestd1; g_pi[o1] = bi1; g_ps[o1] = s1;
}

// ------------------------- kernel 3: combine + losses + output -------------
__global__ void vq_combine(float* __restrict__ out) {
    int n = blockIdx.x * 128 + threadIdx.x;
    const float* pd = g_pd + n * VS;
    const int*   pi = g_pi + n * VS;
    const float* ps = g_ps + n * VS;

    float bestd = 3.4e38f; int bi = 0; float S = 0.f;
#pragma unroll
    for (int sp = 0; sp < VS; sp++) {
        float d = pd[sp];
        if (d < bestd) { bestd = d; bi = pi[sp]; }  // first-min across ordered splits
        S += ps[sp];
    }
    float lse = lg2f(S) * LN2;

    const float4* ep = (const float4*)(g_en + bi * C_DIM);
    const float4* zp = (const float4*)(g_zfn + n * C_DIM);
    int b = n >> 10, hw = n & 1023;
    float* op = out + b * (C_DIM * 1024) + hw;
    float dot = 0.f, vq = 0.f;
#pragma unroll
    for (int i = 0; i < 8; i++) {
        float4 e = ep[i], zt = zp[i];
        dot = fmaf(e.x, zt.x, fmaf(e.y, zt.y, fmaf(e.z, zt.z, fmaf(e.w, zt.w, dot))));
        float dx = e.x - zt.x, dy = e.y - zt.y, dz = e.z - zt.z, dw = e.w - zt.w;
        vq = fmaf(dx, dx, fmaf(dy, dy, fmaf(dz, dz, fmaf(dw, dw, vq))));
        op[(4 * i + 0) * 1024] = e.x;
        op[(4 * i + 1) * 1024] = e.y;
        op[(4 * i + 2) * 1024] = e.z;
        op[(4 * i + 3) * 1024] = e.w;
    }
    float commit = lse - dot;

    // block reduce: 4 warps
    __shared__ float sred[8];
    float v1 = vq, c1 = commit;
#pragma unroll
    for (int o = 16; o; o >>= 1) {
        v1 += __shfl_down_sync(~0u, v1, o);
        c1 += __shfl_down_sync(~0u, c1, o);
    }
    int wid = threadIdx.x >> 5, lid = threadIdx.x & 31;
    if (lid == 0) { sred[wid] = v1; sred[wid + 4] = c1; }
    __syncthreads();
    if (threadIdx.x == 0) {
        float vsum = sred[0] + sred[1] + sred[2] + sred[3];
        float csum = sred[4] + sred[5] + sred[6] + sred[7];
        g_blk[blockIdx.x][0] = vsum;
        g_blk[blockIdx.x][1] = csum;
        __threadfence();
        int t = atomicAdd(&g_cnt, 1);
        if (t == 63) {                       // last block finalizes
            float va = 0.f, ca = 0.f;
            for (int i = 0; i < 64; i++) { va += g_blk[i][0]; ca += g_blk[i][1]; }
            out[N_TOK * C_DIM]     = va / (float)(N_TOK * C_DIM);   // vq_loss
            out[N_TOK * C_DIM + 1] = 0.25f * (ca / (float)N_TOK);   // commit_loss
            g_cnt = 0;                       // reset for graph replay
        }
    }
}

// ---------------------------------------------------------------------------
extern "C" void kernel_launch(void* const* d_in, const int* in_sizes, int n_in,
                              void* d_out, int out_size) {
    const float* z = (const float*)d_in[0];
    const float* emb = (const float*)d_in[1];
    if (n_in >= 2 && in_sizes[0] == V_CODES * C_DIM && in_sizes[1] == N_TOK * 8) {
        const float* t = z; z = emb; emb = t;
    }
    prep<<<64, 256>>>(z, emb);
    dim3 grid(N_TOK / TOKB, VS);
    vq_main<<<grid, TPB>>>();
    vq_combine<<<N_TOK / 128, 128>>>((float*)d_out);
    (void)out_size;
}

// round 6
// speedup vs baseline: 1.1767x; 1.1767x over previous
#include <cuda_runtime.h>
#include <cuda_bf16.h>
#include <cstdint>

// VectorQuantizer fwd: N=8192 tokens, V=8192 codes, C=32.
// S = zfn@en^T as ONE bf16 GEMM with K=192 (6-term bf16 split ~ fp32 exact),
// computed with mma.sync.m16n8k16 (sm_80+ PTX; no tcgen05 -- ptxas targets sm_100).
// log2e folded into A: accum u = log2e*dot. dist~ = esq*log2e - 2u (same argmin).
// commit = lse - dot ; vq = mean (en[idx]-zfn)^2 ; out = en[idx] in NCHW.

#define N_TOK 8192
#define V_CODES 8192
#define C_DIM 32
#define VS 2
#define VPB (V_CODES / VS)      // 4096 codes per block
#define TILE 64                 // codes per smem tile
#define NTIL (VPB / TILE)       // 64 tiles
#define TOKB 128                // tokens per block (16 per warp)
#define KK 96                   // u32 (bf16x2) words per row: K=192
#define RSW 100                 // padded smem row stride in u32 (400B): conflict-free
#define BUF_BYTES (TILE * RSW * 4)     // 25600
#define SMEM_DYN (2 * BUF_BYTES + 2 * TILE * 4 + 64)
#define L2E 1.4426950408889634f
#define LN2 0.6931471805599453f
#define L2EPS 1e-12f

typedef unsigned int u32;

__device__ __align__(16) u32   g_abf[N_TOK * KK];    // A rows (tokens), k-packed bf16x2
__device__ __align__(16) u32   g_bbf[V_CODES * KK];  // B rows (codes), k-packed bf16x2
__device__ __align__(16) float g_en[V_CODES * C_DIM];
__device__ __align__(16) float g_esq2[V_CODES];      // esq * log2e
__device__ __align__(16) float g_zfn[N_TOK * C_DIM];
__device__ float g_pd[N_TOK * VS];
__device__ int   g_pi[N_TOK * VS];
__device__ float g_ps[N_TOK * VS];
__device__ int   g_idx[N_TOK];
__device__ float g_blk[32][2];
__device__ int   g_cnt;

__device__ __forceinline__ u32 smem_u32(const void* p) {
    u32 a;
    asm("{ .reg .u64 t; cvta.to.shared.u64 t, %1; cvt.u32.u64 %0, t; }" : "=r"(a) : "l"(p));
    return a;
}
__device__ __forceinline__ void cpa16(u32 s, const void* g) {
    asm volatile("cp.async.cg.shared.global [%0], [%1], 16;" :: "r"(s), "l"(g));
}
__device__ __forceinline__ void cpa_commit() { asm volatile("cp.async.commit_group;" ::: "memory"); }
template <int N> __device__ __forceinline__ void cpa_wait() {
    asm volatile("cp.async.wait_group %0;" :: "n"(N) : "memory");
}
__device__ __forceinline__ void ldm_x4(u32& r0, u32& r1, u32& r2, u32& r3, u32 addr) {
    asm volatile("ldmatrix.sync.aligned.m8n8.x4.shared.b16 {%0,%1,%2,%3}, [%4];"
                 : "=r"(r0), "=r"(r1), "=r"(r2), "=r"(r3) : "r"(addr));
}
__device__ __forceinline__ void mma16816(float* c, u32 a0, u32 a1, u32 a2, u32 a3,
                                         u32 b0, u32 b1) {
    asm volatile("mma.sync.aligned.m16n8k16.row.col.f32.bf16.bf16.f32 "
                 "{%0,%1,%2,%3}, {%4,%5,%6,%7}, {%8,%9}, {%0,%1,%2,%3};"
                 : "+f"(c[0]), "+f"(c[1]), "+f"(c[2]), "+f"(c[3])
                 : "r"(a0), "r"(a1), "r"(a2), "r"(a3), "r"(b0), "r"(b1));
}
__device__ __forceinline__ float ex2f(float x) {
    float r; asm("ex2.approx.f32 %0, %1;" : "=f"(r) : "f"(x)); return r;
}
__device__ __forceinline__ float lg2f(float x) {
    float r; asm("lg2.approx.f32 %0, %1;" : "=f"(r) : "f"(x)); return r;
}
__device__ __forceinline__ u32 packbf(__nv_bfloat16 a, __nv_bfloat16 b) {
    return (u32)__bfloat16_as_ushort(a) | ((u32)__bfloat16_as_ushort(b) << 16);
}

// ---- kernel 1: prep -------------------------------------------------------
// blocks 0-31: codebook -> g_en, g_esq2, g_bbf ; blocks 32-63: tokens -> g_zfn, g_abf
__global__ void prep(const float* __restrict__ z, const float* __restrict__ emb) {
    int tid = threadIdx.x;
    float val[C_DIM];
    __nv_bfloat16 h1[C_DIM], h2[C_DIM], h3[C_DIM];

    if (blockIdx.x < 32) {
        int r = blockIdx.x * 256 + tid;
        const float4* src = (const float4*)(emb + r * C_DIM);
        float ss = 0.f;
#pragma unroll
        for (int i = 0; i < 8; i++) {
            float4 v = src[i];
            val[4 * i] = v.x; val[4 * i + 1] = v.y; val[4 * i + 2] = v.z; val[4 * i + 3] = v.w;
            ss += v.x * v.x + v.y * v.y + v.z * v.z + v.w * v.w;
        }
        float rcp = 1.0f / fmaxf(sqrtf(ss), L2EPS);
        float es = 0.f;
        float4* dst = (float4*)(g_en + r * C_DIM);
#pragma unroll
        for (int c = 0; c < C_DIM; c++) { val[c] *= rcp; es = fmaf(val[c], val[c], es); }
#pragma unroll
        for (int i = 0; i < 8; i++)
            dst[i] = make_float4(val[4 * i], val[4 * i + 1], val[4 * i + 2], val[4 * i + 3]);
        g_esq2[r] = es * L2E;
#pragma unroll
        for (int c = 0; c < C_DIM; c++) {
            h1[c] = __float2bfloat16_rn(val[c]);
            float r1 = val[c] - __bfloat162float(h1[c]);
            h2[c] = __float2bfloat16_rn(r1);
            h3[c] = __float2bfloat16_rn(r1 - __bfloat162float(h2[c]));
        }
        const __nv_bfloat16* segs[6] = { h1, h2, h1, h3, h2, h1 };  // B: e1 e2 e1 e3 e2 e1
        u32* brow = g_bbf + (size_t)r * KK;
#pragma unroll
        for (int s = 0; s < 6; s++)
#pragma unroll
            for (int q = 0; q < 16; q++)
                brow[s * 16 + q] = packbf(segs[s][2 * q], segs[s][2 * q + 1]);
    } else {
        int n = (blockIdx.x - 32) * 256 + tid;
        int b = n >> 10, hw = n & 1023;
        const float* zp = z + b * (C_DIM * 1024) + hw;
        float ss = 0.f;
#pragma unroll
        for (int c = 0; c < C_DIM; c++) { val[c] = zp[c * 1024]; ss = fmaf(val[c], val[c], ss); }
        float rcp = 1.0f / fmaxf(sqrtf(ss), L2EPS);
        float4* dst = (float4*)(g_zfn + n * C_DIM);
#pragma unroll
        for (int i = 0; i < 8; i++)
            dst[i] = make_float4(val[4 * i] * rcp, val[4 * i + 1] * rcp,
                                 val[4 * i + 2] * rcp, val[4 * i + 3] * rcp);
#pragma unroll
        for (int c = 0; c < C_DIM; c++) {
            float zs = val[c] * rcp * L2E;    // fold log2e into A
            h1[c] = __float2bfloat16_rn(zs);
            float r1 = zs - __bfloat162float(h1[c]);
            h2[c] = __float2bfloat16_rn(r1);
            h3[c] = __float2bfloat16_rn(r1 - __bfloat162float(h2[c]));
        }
        const __nv_bfloat16* segs[6] = { h1, h1, h2, h1, h2, h3 };  // A: z1 z1 z2 z1 z2 z3
        u32* arow = g_abf + (size_t)n * KK;
#pragma unroll
        for (int s = 0; s < 6; s++)
#pragma unroll
            for (int q = 0; q < 16; q++)
                arow[s * 16 + q] = packbf(segs[s][2 * q], segs[s][2 * q + 1]);
    }
}

// ---- kernel 2: HMMA similarity scan ---------------------------------------
// grid (64, 2). Block: 128 tokens x 4096 codes. 8 warps, warp = 16 token rows.
__global__ __launch_bounds__(256) void vq_main() {
    extern __shared__ __align__(16) char dsm[];
    u32 sb = smem_u32(dsm);                  // [2][TILE*RSW] u32
    float* sE = (float*)(dsm + 2 * BUF_BYTES);  // [2][TILE]

    int tid = threadIdx.x;
    int w = tid >> 5, lane = tid & 31;
    int g = lane >> 2, tg = lane & 3;
    int Rb = blockIdx.x * TOKB + w * 16;
    int vbase = blockIdx.y * VPB;

    // A fragments: 12 k-steps x 4 regs, loaded once from global.
    u32 af[12][4];
    {
        const u32* A0 = g_abf + (size_t)(Rb + g) * KK;
        const u32* A8 = g_abf + (size_t)(Rb + g + 8) * KK;
#pragma unroll
        for (int ks = 0; ks < 12; ks++) {
            af[ks][0] = A0[ks * 8 + tg];
            af[ks][1] = A8[ks * 8 + tg];
            af[ks][2] = A0[ks * 8 + tg + 4];
            af[ks][3] = A8[ks * 8 + tg + 4];
        }
    }

    // ldmatrix per-thread row offset: matrix m = lane/8, row r = lane%8
    // row-in-tile = nbp*16 + ((m>=2)?8:0) + r ; byte = row*400 + ks*32 + (m&1)*16
    u32 lm_off = (u32)((((lane >> 4) & 1) * 8 + (lane & 7)) * (RSW * 4) + ((lane >> 3) & 1) * 16);

    // prologue: stage tile 0
    {
        const char* gs = (const char*)(g_bbf + (size_t)vbase * KK);
#pragma unroll
        for (int p = 0; p < 6; p++) {
            int ch = tid + p * 256;                 // 1536 chunks of 16B
            int row = ch / 24, col = ch % 24;
            cpa16(sb + (u32)(row * (RSW * 4) + col * 16), gs + (size_t)row * 384 + col * 16);
        }
        if (tid < 16) cpa16(smem_u32(sE) + (u32)tid * 16, (const char*)(g_esq2 + vbase) + tid * 16);
        cpa_commit();
    }

    float bd0 = 3.4e38f, bd1 = 3.4e38f, ss0 = 0.f, ss1 = 0.f;
    int bi0 = 0, bi1 = 0;

    for (int i = 0; i < NTIL; i++) {
        int buf = i & 1;
        if (i + 1 < NTIL) {
            int nb = (i + 1) & 1;
            const char* gs = (const char*)(g_bbf + (size_t)(vbase + (i + 1) * TILE) * KK);
            u32 sd = sb + (u32)nb * BUF_BYTES;
#pragma unroll
            for (int p = 0; p < 6; p++) {
                int ch = tid + p * 256;
                int row = ch / 24, col = ch % 24;
                cpa16(sd + (u32)(row * (RSW * 4) + col * 16), gs + (size_t)row * 384 + col * 16);
            }
            if (tid < 16) cpa16(smem_u32(sE + nb * TILE) + (u32)tid * 16,
                                (const char*)(g_esq2 + vbase + (i + 1) * TILE) + tid * 16);
            cpa_commit();
            cpa_wait<1>();
        } else {
            cpa_wait<0>();
        }
        __syncthreads();

        u32 bbase = sb + (u32)buf * BUF_BYTES + lm_off;
        float acc[8][4];
#pragma unroll
        for (int nb = 0; nb < 8; nb++)
#pragma unroll
            for (int q = 0; q < 4; q++) acc[nb][q] = 0.f;

#pragma unroll
        for (int ks = 0; ks < 12; ks++) {
#pragma unroll
            for (int nbp = 0; nbp < 4; nbp++) {
                u32 b00, b01, b10, b11;
                ldm_x4(b00, b01, b10, b11,
                       bbase + (u32)(nbp * 16 * (RSW * 4) + ks * 32));
                mma16816(acc[2 * nbp],     af[ks][0], af[ks][1], af[ks][2], af[ks][3], b00, b01);
                mma16816(acc[2 * nbp + 1], af[ks][0], af[ks][1], af[ks][2], af[ks][3], b10, b11);
            }
        }

        // epilogue: acc[nb] = {u(g,c0), u(g,c1), u(g+8,c0), u(g+8,c1)}, c0=2tg
        const float* se = sE + buf * TILE;
        int cb = vbase + i * TILE + 2 * tg;
#pragma unroll
        for (int nb = 0; nb < 8; nb++) {
            float2 e = *(const float2*)(se + nb * 8 + 2 * tg);
            int c0 = cb + nb * 8, c1 = c0 + 1;
            float d;
            d = fmaf(-2.f, acc[nb][0], e.x); if (d < bd0) { bd0 = d; bi0 = c0; }
            d = fmaf(-2.f, acc[nb][1], e.y); if (d < bd0) { bd0 = d; bi0 = c1; }
            d = fmaf(-2.f, acc[nb][2], e.x); if (d < bd1) { bd1 = d; bi1 = c0; }
            d = fmaf(-2.f, acc[nb][3], e.y); if (d < bd1) { bd1 = d; bi1 = c1; }
            ss0 += ex2f(acc[nb][0]) + ex2f(acc[nb][1]);
            ss1 += ex2f(acc[nb][2]) + ex2f(acc[nb][3]);
        }
        __syncthreads();
    }

    // reduce across the 4 threads of each row-group (width=4 => quads)
#pragma unroll
    for (int o = 1; o < 4; o <<= 1) {
        float od = __shfl_down_sync(~0u, bd0, o, 4);
        int   oi = __shfl_down_sync(~0u, bi0, o, 4);
        float os = __shfl_down_sync(~0u, ss0, o, 4);
        if (od < bd0 || (od == bd0 && oi < bi0)) { bd0 = od; bi0 = oi; }
        ss0 += os;
        od = __shfl_down_sync(~0u, bd1, o, 4);
        oi = __shfl_down_sync(~0u, bi1, o, 4);
        os = __shfl_down_sync(~0u, ss1, o, 4);
        if (od < bd1 || (od == bd1 && oi < bi1)) { bd1 = od; bi1 = oi; }
        ss1 += os;
    }
    if (tg == 0) {
        int o0 = (Rb + g) * VS + blockIdx.y;
        int o1 = (Rb + g + 8) * VS + blockIdx.y;
        g_pd[o0] = bd0; g_pi[o0] = bi0; g_ps[o0] = ss0;
        g_pd[o1] = bd1; g_pi[o1] = bi1; g_ps[o1] = ss1;
    }
}

// ---- kernel 3: merge splits + losses --------------------------------------
__global__ void vq_reduce(float* __restrict__ out) {
    int n = blockIdx.x * 256 + threadIdx.x;
    float2 pd = *(const float2*)(g_pd + n * VS);
    int2   pi = *(const int2*)(g_pi + n * VS);
    float2 ps = *(const float2*)(g_ps + n * VS);

    float bd = pd.x; int bi = pi.x;
    if (pd.y < bd || (pd.y == bd && pi.y < bi)) { bd = pd.y; bi = pi.y; }
    float S = ps.x + ps.y;
    float lse = lg2f(S) * LN2;

    const float4* ep = (const float4*)(g_en + (size_t)bi * C_DIM);
    const float4* zp = (const float4*)(g_zfn + (size_t)n * C_DIM);
    float dot = 0.f, vq = 0.f;
#pragma unroll
    for (int i = 0; i < 8; i++) {
        float4 e = ep[i], zt = zp[i];
        dot = fmaf(e.x, zt.x, fmaf(e.y, zt.y, fmaf(e.z, zt.z, fmaf(e.w, zt.w, dot))));
        float dx = e.x - zt.x, dy = e.y - zt.y, dz = e.z - zt.z, dw = e.w - zt.w;
        vq = fmaf(dx, dx, fmaf(dy, dy, fmaf(dz, dz, fmaf(dw, dw, vq))));
    }
    g_idx[n] = bi;
    float commit = lse - dot;

    __shared__ float sred[16];
    float v1 = vq, c1 = commit;
#pragma unroll
    for (int o = 16; o; o >>= 1) {
        v1 += __shfl_down_sync(~0u, v1, o);
        c1 += __shfl_down_sync(~0u, c1, o);
    }
    int wid = threadIdx.x >> 5, lid = threadIdx.x & 31;
    if (lid == 0) { sred[wid] = v1; sred[wid + 8] = c1; }
    __syncthreads();
    if (threadIdx.x == 0) {
        float vs = 0.f, cs = 0.f;
#pragma unroll
        for (int i = 0; i < 8; i++) { vs += sred[i]; cs += sred[i + 8]; }
        g_blk[blockIdx.x][0] = vs; g_blk[blockIdx.x][1] = cs;
        __threadfence();
        if (atomicAdd(&g_cnt, 1) == 31) {
            float va = 0.f, ca = 0.f;
            for (int i = 0; i < 32; i++) { va += g_blk[i][0]; ca += g_blk[i][1]; }
            out[N_TOK * C_DIM]     = va / (float)(N_TOK * C_DIM);
            out[N_TOK * C_DIM + 1] = 0.25f * (ca / (float)N_TOK);
            g_cnt = 0;
        }
    }
}

// ---- kernel 4: NCHW scatter -----------------------------------------------
__global__ void vq_scatter(float* __restrict__ out) {
    int gidx = blockIdx.x * 256 + threadIdx.x;
    int q = gidx >> 13, n = gidx & (N_TOK - 1);
    int bi = g_idx[n];
    float4 e = ((const float4*)(g_en + (size_t)bi * C_DIM))[q];
    int b = n >> 10, hw = n & 1023;
    float* op = out + b * (C_DIM * 1024) + (4 * q) * 1024 + hw;
    op[0] = e.x; op[1024] = e.y; op[2048] = e.z; op[3072] = e.w;
}

// ---------------------------------------------------------------------------
extern "C" void kernel_launch(void* const* d_in, const int* in_sizes, int n_in,
                              void* d_out, int out_size) {
    const float* z = (const float*)d_in[0];
    const float* emb = (const float*)d_in[1];
    if (n_in >= 2 && in_sizes[0] == V_CODES * C_DIM && in_sizes[1] == N_TOK * 8) {
        const float* t = z; z = emb; emb = t;
    }
    cudaFuncSetAttribute(vq_main, cudaFuncAttributeMaxDynamicSharedMemorySize, SMEM_DYN);
    prep<<<64, 256>>>(z, emb);
    dim3 grid(N_TOK / TOKB, VS);
    vq_main<<<grid, 256, SMEM_DYN>>>();
    vq_reduce<<<N_TOK / 256, 256>>>((float*)d_out);
    vq_scatter<<<N_TOK * 8 / 256, 256>>>((float*)d_out);
    (void)out_size;
}

// round 8
// speedup vs baseline: 1.8089x; 1.5373x over previous
#include <cuda_runtime.h>
#include <cuda_fp16.h>
#include <cstdint>

// VectorQuantizer fwd: N=8192 tokens, V=8192 codes, C=32.
// S = zfn@en^T via mma.sync.m16n8k16 fp16, K=96 (3-product fp16 split):
//   u = z1e1  +  2^-12 * ( z1*(e2*2^12) + (z2*2^12)*e1 )   ~ fp32-exact
// (residuals scaled by 2^12 into the fp16 normal range; separate accumulator,
//  recombined with one FFMA). log2e folded into A: u = log2e*dot.
// dist~ = esq*log2e - 2u (same argmin). commit = lse - dot(exact fp32 redo).

#define N_TOK 8192
#define V_CODES 8192
#define C_DIM 32
#define VS 2
#define VPB (V_CODES / VS)      // 4096 codes per block
#define TILE 64                 // codes per smem tile
#define NTIL (VPB / TILE)       // 64 tiles
#define TOKB 128                // tokens per block (16 per warp)
#define KK 48                   // u32 (fp16x2) words per row: K=96
#define RSW 52                  // padded smem row stride in u32 (208B)
#define BUF_BYTES (TILE * RSW * 4)     // 13312
#define SMEM_DYN (2 * BUF_BYTES + 2 * TILE * 4 + 64)
#define L2E 1.4426950408889634f
#define LN2 0.6931471805599453f
#define L2EPS 1e-12f
#define RSCALE 4096.0f
#define RINV 0.000244140625f    // 2^-12

typedef unsigned int u32;

__device__ __align__(16) u32   g_abf[N_TOK * KK];    // A rows: [z1 | z1 | z2'] fp16x2
__device__ __align__(16) u32   g_bbf[V_CODES * KK];  // B rows: [e1 | e2' | e1] fp16x2
__device__ __align__(16) float g_en[V_CODES * C_DIM];
__device__ __align__(16) float g_esq2[V_CODES];      // esq * log2e
__device__ __align__(16) float g_zfn[N_TOK * C_DIM];
__device__ float g_pd[N_TOK * VS];
__device__ int   g_pi[N_TOK * VS];
__device__ float g_ps[N_TOK * VS];
__device__ int   g_idx[N_TOK];
__device__ float g_blk[32][2];
__device__ int   g_cnt;

__device__ __forceinline__ u32 smem_u32(const void* p) {
    u32 a;
    asm("{ .reg .u64 t; cvta.to.shared.u64 t, %1; cvt.u32.u64 %0, t; }" : "=r"(a) : "l"(p));
    return a;
}
__device__ __forceinline__ void cpa16(u32 s, const void* g) {
    asm volatile("cp.async.cg.shared.global [%0], [%1], 16;" :: "r"(s), "l"(g));
}
__device__ __forceinline__ void cpa_commit() { asm volatile("cp.async.commit_group;" ::: "memory"); }
template <int N> __device__ __forceinline__ void cpa_wait() {
    asm volatile("cp.async.wait_group %0;" :: "n"(N) : "memory");
}
__device__ __forceinline__ void ldm_x4(u32& r0, u32& r1, u32& r2, u32& r3, u32 addr) {
    asm volatile("ldmatrix.sync.aligned.m8n8.x4.shared.b16 {%0,%1,%2,%3}, [%4];"
                 : "=r"(r0), "=r"(r1), "=r"(r2), "=r"(r3) : "r"(addr));
}
__device__ __forceinline__ void mma16816(float* c, u32 a0, u32 a1, u32 a2, u32 a3,
                                         u32 b0, u32 b1) {
    asm volatile("mma.sync.aligned.m16n8k16.row.col.f32.f16.f16.f32 "
                 "{%0,%1,%2,%3}, {%4,%5,%6,%7}, {%8,%9}, {%0,%1,%2,%3};"
                 : "+f"(c[0]), "+f"(c[1]), "+f"(c[2]), "+f"(c[3])
                 : "r"(a0), "r"(a1), "r"(a2), "r"(a3), "r"(b0), "r"(b1));
}
__device__ __forceinline__ float ex2f(float x) {
    float r; asm("ex2.approx.f32 %0, %1;" : "=f"(r) : "f"(x)); return r;
}
__device__ __forceinline__ float lg2f(float x) {
    float r; asm("lg2.approx.f32 %0, %1;" : "=f"(r) : "f"(x)); return r;
}
__device__ __forceinline__ u32 packh(__half a, __half b) {
    __half2 h = __halves2half2(a, b);
    return *(u32*)&h;
}

// ---- kernel 1: prep -------------------------------------------------------
// blocks 0-31: codebook -> g_en, g_esq2, g_bbf ; blocks 32-63: tokens -> g_zfn, g_abf
__global__ void prep(const float* __restrict__ z, const float* __restrict__ emb) {
    int tid = threadIdx.x;
    float val[C_DIM];
    __half h1[C_DIM], h2[C_DIM];

    if (blockIdx.x < 32) {
        int r = blockIdx.x * 256 + tid;
        const float4* src = (const float4*)(emb + r * C_DIM);
        float ss = 0.f;
#pragma unroll
        for (int i = 0; i < 8; i++) {
            float4 v = src[i];
            val[4 * i] = v.x; val[4 * i + 1] = v.y; val[4 * i + 2] = v.z; val[4 * i + 3] = v.w;
            ss += v.x * v.x + v.y * v.y + v.z * v.z + v.w * v.w;
        }
        float rcp = 1.0f / fmaxf(sqrtf(ss), L2EPS);
        float es = 0.f;
        float4* dst = (float4*)(g_en + r * C_DIM);
#pragma unroll
        for (int c = 0; c < C_DIM; c++) { val[c] *= rcp; es = fmaf(val[c], val[c], es); }
#pragma unroll
        for (int i = 0; i < 8; i++)
            dst[i] = make_float4(val[4 * i], val[4 * i + 1], val[4 * i + 2], val[4 * i + 3]);
        g_esq2[r] = es * L2E;
#pragma unroll
        for (int c = 0; c < C_DIM; c++) {
            h1[c] = __float2half_rn(val[c]);
            h2[c] = __float2half_rn((val[c] - __half2float(h1[c])) * RSCALE);
        }
        const __half* segs[3] = { h1, h2, h1 };       // B: e1 | e2' | e1
        u32* brow = g_bbf + (size_t)r * KK;
#pragma unroll
        for (int s = 0; s < 3; s++)
#pragma unroll
            for (int q = 0; q < 16; q++)
                brow[s * 16 + q] = packh(segs[s][2 * q], segs[s][2 * q + 1]);
    } else {
        int n = (blockIdx.x - 32) * 256 + tid;
        int b = n >> 10, hw = n & 1023;
        const float* zp = z + b * (C_DIM * 1024) + hw;
        float ss = 0.f;
#pragma unroll
        for (int c = 0; c < C_DIM; c++) { val[c] = zp[c * 1024]; ss = fmaf(val[c], val[c], ss); }
        float rcp = 1.0f / fmaxf(sqrtf(ss), L2EPS);
        float4* dst = (float4*)(g_zfn + n * C_DIM);
#pragma unroll
        for (int i = 0; i < 8; i++)
            dst[i] = make_float4(val[4 * i] * rcp, val[4 * i + 1] * rcp,
                                 val[4 * i + 2] * rcp, val[4 * i + 3] * rcp);
#pragma unroll
        for (int c = 0; c < C_DIM; c++) {
            float zs = val[c] * rcp * L2E;            // fold log2e into A
            h1[c] = __float2half_rn(zs);
            h2[c] = __float2half_rn((zs - __half2float(h1[c])) * RSCALE);
        }
        const __half* segs[3] = { h1, h1, h2 };       // A: z1 | z1 | z2'
        u32* arow = g_abf + (size_t)n * KK;
#pragma unroll
        for (int s = 0; s < 3; s++)
#pragma unroll
            for (int q = 0; q < 16; q++)
                arow[s * 16 + q] = packh(segs[s][2 * q], segs[s][2 * q + 1]);
    }
}

// ---- kernel 2: HMMA similarity scan ---------------------------------------
// grid (64, 2). Block: 128 tokens x 4096 codes. 8 warps, warp = 16 token rows.
__global__ __launch_bounds__(256) void vq_main() {
    extern __shared__ __align__(16) char dsm[];
    u32 sb = smem_u32(dsm);                      // [2][TILE*RSW] u32
    float* sE = (float*)(dsm + 2 * BUF_BYTES);   // [2][TILE]

    int tid = threadIdx.x;
    int w = tid >> 5, lane = tid & 31;
    int g = lane >> 2, tg = lane & 3;
    int Rb = blockIdx.x * TOKB + w * 16;
    int vbase = blockIdx.y * VPB;

    // A fragments: 6 k16-steps x 4 regs, loaded once from global.
    u32 af[6][4];
    {
        const u32* A0 = g_abf + (size_t)(Rb + g) * KK;
        const u32* A8 = g_abf + (size_t)(Rb + g + 8) * KK;
#pragma unroll
        for (int ks = 0; ks < 6; ks++) {
            af[ks][0] = A0[ks * 8 + tg];
            af[ks][1] = A8[ks * 8 + tg];
            af[ks][2] = A0[ks * 8 + tg + 4];
            af[ks][3] = A8[ks * 8 + tg + 4];
        }
    }

    // ldmatrix per-thread offset: row = ((lane>>4)&1)*8 + (lane&7), col-half = (lane>>3)&1
    u32 lm_off = (u32)((((lane >> 4) & 1) * 8 + (lane & 7)) * (RSW * 4) + ((lane >> 3) & 1) * 16);

    // prologue: stage tile 0 (64 rows x 192B = 768 16B-chunks)
    {
        const char* gs = (const char*)(g_bbf + (size_t)vbase * KK);
#pragma unroll
        for (int p = 0; p < 3; p++) {
            int ch = tid + p * 256;
            int row = ch / 12, col = ch % 12;
            cpa16(sb + (u32)(row * (RSW * 4) + col * 16), gs + (size_t)row * 192 + col * 16);
        }
        if (tid < 16) cpa16(smem_u32(sE) + (u32)tid * 16, (const char*)(g_esq2 + vbase) + tid * 16);
        cpa_commit();
    }

    float bd0 = 3.4e38f, bd1 = 3.4e38f, ss0 = 0.f, ss1 = 0.f;
    int bi0 = 0, bi1 = 0;

    for (int i = 0; i < NTIL; i++) {
        int buf = i & 1;
        if (i + 1 < NTIL) {
            int nb = (i + 1) & 1;
            const char* gs = (const char*)(g_bbf + (size_t)(vbase + (i + 1) * TILE) * KK);
            u32 sd = sb + (u32)nb * BUF_BYTES;
#pragma unroll
            for (int p = 0; p < 3; p++) {
                int ch = tid + p * 256;
                int row = ch / 12, col = ch % 12;
                cpa16(sd + (u32)(row * (RSW * 4) + col * 16), gs + (size_t)row * 192 + col * 16);
            }
            if (tid < 16) cpa16(smem_u32(sE + nb * TILE) + (u32)tid * 16,
                                (const char*)(g_esq2 + vbase + (i + 1) * TILE) + tid * 16);
            cpa_commit();
            cpa_wait<1>();
        } else {
            cpa_wait<0>();
        }
        __syncthreads();

        u32 bbase = sb + (u32)buf * BUF_BYTES + lm_off;
        float acc1[8][4], acc2[8][4];
#pragma unroll
        for (int nb = 0; nb < 8; nb++)
#pragma unroll
            for (int q = 0; q < 4; q++) { acc1[nb][q] = 0.f; acc2[nb][q] = 0.f; }

#pragma unroll
        for (int ks = 0; ks < 6; ks++) {
            float (*acc)[4] = (ks < 2) ? acc1 : acc2;   // seg0 -> main, segs 1-2 -> residual
#pragma unroll
            for (int nbp = 0; nbp < 4; nbp++) {
                u32 b00, b01, b10, b11;
                ldm_x4(b00, b01, b10, b11,
                       bbase + (u32)(nbp * 16 * (RSW * 4) + ks * 32));
                mma16816(acc[2 * nbp],     af[ks][0], af[ks][1], af[ks][2], af[ks][3], b00, b01);
                mma16816(acc[2 * nbp + 1], af[ks][0], af[ks][1], af[ks][2], af[ks][3], b10, b11);
            }
        }

        // epilogue: u = acc1 + 2^-12*acc2 ; rows {g, g+8}, cols {c0, c0+1}
        const float* se = sE + buf * TILE;
        int cb = vbase + i * TILE + 2 * tg;
#pragma unroll
        for (int nb = 0; nb < 8; nb++) {
            float2 e = *(const float2*)(se + nb * 8 + 2 * tg);
            int c0 = cb + nb * 8, c1 = c0 + 1;
            float u00 = fmaf(acc2[nb][0], RINV, acc1[nb][0]);
            float u01 = fmaf(acc2[nb][1], RINV, acc1[nb][1]);
            float u10 = fmaf(acc2[nb][2], RINV, acc1[nb][2]);
            float u11 = fmaf(acc2[nb][3], RINV, acc1[nb][3]);
            float d;
            d = fmaf(-2.f, u00, e.x); if (d < bd0) { bd0 = d; bi0 = c0; }
            d = fmaf(-2.f, u01, e.y); if (d < bd0) { bd0 = d; bi0 = c1; }
            d = fmaf(-2.f, u10, e.x); if (d < bd1) { bd1 = d; bi1 = c0; }
            d = fmaf(-2.f, u11, e.y); if (d < bd1) { bd1 = d; bi1 = c1; }
            ss0 += ex2f(u00) + ex2f(u01);
            ss1 += ex2f(u10) + ex2f(u11);
        }
        __syncthreads();
    }

    // reduce across the 4 threads of each row-group (quads)
#pragma unroll
    for (int o = 1; o < 4; o <<= 1) {
        float od = __shfl_down_sync(~0u, bd0, o, 4);
        int   oi = __shfl_down_sync(~0u, bi0, o, 4);
        float os = __shfl_down_sync(~0u, ss0, o, 4);
        if (od < bd0 || (od == bd0 && oi < bi0)) { bd0 = od; bi0 = oi; }
        ss0 += os;
        od = __shfl_down_sync(~0u, bd1, o, 4);
        oi = __shfl_down_sync(~0u, bi1, o, 4);
        os = __shfl_down_sync(~0u, ss1, o, 4);
        if (od < bd1 || (od == bd1 && oi < bi1)) { bd1 = od; bi1 = oi; }
        ss1 += os;
    }
    if (tg == 0) {
        int o0 = (Rb + g) * VS + blockIdx.y;
        int o1 = (Rb + g + 8) * VS + blockIdx.y;
        g_pd[o0] = bd0; g_pi[o0] = bi0; g_ps[o0] = ss0;
        g_pd[o1] = bd1; g_pi[o1] = bi1; g_ps[o1] = ss1;
    }
}

// ---- kernel 3: merge splits + losses --------------------------------------
__global__ void vq_reduce(float* __restrict__ out) {
    int n = blockIdx.x * 256 + threadIdx.x;
    float2 pd = *(const float2*)(g_pd + n * VS);
    int2   pi = *(const int2*)(g_pi + n * VS);
    float2 ps = *(const float2*)(g_ps + n * VS);

    float bd = pd.x; int bi = pi.x;
    if (pd.y < bd || (pd.y == bd && pi.y < bi)) { bd = pd.y; bi = pi.y; }
    float S = ps.x + ps.y;
    float lse = lg2f(S) * LN2;

    const float4* ep = (const float4*)(g_en + (size_t)bi * C_DIM);
    const float4* zp = (const float4*)(g_zfn + (size_t)n * C_DIM);
    float dot = 0.f, vq = 0.f;
#pragma unroll
    for (int i = 0; i < 8; i++) {
        float4 e = ep[i], zt = zp[i];
        dot = fmaf(e.x, zt.x, fmaf(e.y, zt.y, fmaf(e.z, zt.z, fmaf(e.w, zt.w, dot))));
        float dx = e.x - zt.x, dy = e.y - zt.y, dz = e.z - zt.z, dw = e.w - zt.w;
        vq = fmaf(dx, dx, fmaf(dy, dy, fmaf(dz, dz, fmaf(dw, dw, vq))));
    }
    g_idx[n] = bi;
    float commit = lse - dot;

    __shared__ float sred[16];
    float v1 = vq, c1 = commit;
#pragma unroll
    for (int o = 16; o; o >>= 1) {
        v1 += __shfl_down_sync(~0u, v1, o);
        c1 += __shfl_down_sync(~0u, c1, o);
    }
    int wid = threadIdx.x >> 5, lid = threadIdx.x & 31;
    if (lid == 0) { sred[wid] = v1; sred[wid + 8] = c1; }
    __syncthreads();
    if (threadIdx.x == 0) {
        float vs = 0.f, cs = 0.f;
#pragma unroll
        for (int i = 0; i < 8; i++) { vs += sred[i]; cs += sred[i + 8]; }
        g_blk[blockIdx.x][0] = vs; g_blk[blockIdx.x][1] = cs;
        __threadfence();
        if (atomicAdd(&g_cnt, 1) == 31) {
            float va = 0.f, ca = 0.f;
            for (int i = 0; i < 32; i++) { va += g_blk[i][0]; ca += g_blk[i][1]; }
            out[N_TOK * C_DIM]     = va / (float)(N_TOK * C_DIM);
            out[N_TOK * C_DIM + 1] = 0.25f * (ca / (float)N_TOK);
            g_cnt = 0;
        }
    }
}

// ---- kernel 4: NCHW scatter -----------------------------------------------
__global__ void vq_scatter(float* __restrict__ out) {
    int gidx = blockIdx.x * 256 + threadIdx.x;
    int q = gidx >> 13, n = gidx & (N_TOK - 1);
    int bi = g_idx[n];
    float4 e = ((const float4*)(g_en + (size_t)bi * C_DIM))[q];
    int b = n >> 10, hw = n & 1023;
    float* op = out + b * (C_DIM * 1024) + (4 * q) * 1024 + hw;
    op[0] = e.x; op[1024] = e.y; op[2048] = e.z; op[3072] = e.w;
}

// ---------------------------------------------------------------------------
extern "C" void kernel_launch(void* const* d_in, const int* in_sizes, int n_in,
                              void* d_out, int out_size) {
    const float* z = (const float*)d_in[0];
    const float* emb = (const float*)d_in[1];
    if (n_in >= 2 && in_sizes[0] == V_CODES * C_DIM && in_sizes[1] == N_TOK * 8) {
        const float* t = z; z = emb; emb = t;
    }
    cudaFuncSetAttribute(vq_main, cudaFuncAttributeMaxDynamicSharedMemorySize, SMEM_DYN);
    prep<<<64, 256>>>(z, emb);
    dim3 grid(N_TOK / TOKB, VS);
    vq_main<<<grid, 256, SMEM_DYN>>>();
    vq_reduce<<<N_TOK / 256, 256>>>((float*)d_out);
    vq_scatter<<<N_TOK * 8 / 256, 256>>>((float*)d_out);
    (void)out_size;
}

// round 9
// speedup vs baseline: 1.8813x; 1.0400x over previous
#include <cuda_runtime.h>
#include <cuda_fp16.h>
#include <cstdint>

// VectorQuantizer fwd: N=8192 tokens, V=8192 codes, C=32.
// S = zfn@en^T via mma.sync.m16n8k16 fp16, K=96 (3-product fp16 split):
//   u = z1e1 + 2^-12*( z1*(e2*2^12) + (z2*2^12)*e1 )  ~ fp32-exact
// log2e folded into A: u = log2e*dot. dist~ = esq*log2e - 2u (same argmin).
// Software-pipelined: epilogue(t) executes under mma(t+1)'s tensor shadow.
// 16 warps = (row-group 0..7) x (col-half 0..1); acc ping-pong sets.

#define N_TOK 8192
#define V_CODES 8192
#define C_DIM 32
#define YS 2                    // grid.y splits
#define VS 4                    // effective splits per token (y*2 + col-half)
#define VPB (V_CODES / YS)      // 4096 codes per block
#define TILE 64
#define NTIL (VPB / TILE)       // 64 tiles
#define TOKB 128
#define KK 48                   // u32 (fp16x2) words per row: K=96
#define RSW 52                  // padded smem row stride in u32 (208B)
#define BUF_BYTES (TILE * RSW * 4)     // 13312
#define SMEM_DYN (2 * BUF_BYTES + 4 * TILE * 4 + 64)
#define L2E 1.4426950408889634f
#define LN2 0.6931471805599453f
#define L2EPS 1e-12f
#define RSCALE 4096.0f
#define RINV 0.000244140625f    // 2^-12

typedef unsigned int u32;

__device__ __align__(16) u32   g_abf[N_TOK * KK];    // A rows: [z1 | z1 | z2'] fp16x2
__device__ __align__(16) u32   g_bbf[V_CODES * KK];  // B rows: [e1 | e2' | e1] fp16x2
__device__ __align__(16) float g_en[V_CODES * C_DIM];
__device__ __align__(16) float g_esq2[V_CODES];      // esq * log2e
__device__ __align__(16) float g_zfn[N_TOK * C_DIM];
__device__ float g_pd[N_TOK * VS];
__device__ int   g_pi[N_TOK * VS];
__device__ float g_ps[N_TOK * VS];
__device__ float g_blk[32][2];
__device__ int   g_cnt;

__device__ __forceinline__ u32 smem_u32(const void* p) {
    u32 a;
    asm("{ .reg .u64 t; cvta.to.shared.u64 t, %1; cvt.u32.u64 %0, t; }" : "=r"(a) : "l"(p));
    return a;
}
__device__ __forceinline__ void cpa16(u32 s, const void* g) {
    asm volatile("cp.async.cg.shared.global [%0], [%1], 16;" :: "r"(s), "l"(g));
}
__device__ __forceinline__ void cpa_commit() { asm volatile("cp.async.commit_group;" ::: "memory"); }
template <int N> __device__ __forceinline__ void cpa_wait() {
    asm volatile("cp.async.wait_group %0;" :: "n"(N) : "memory");
}
__device__ __forceinline__ void ldm_x4(u32& r0, u32& r1, u32& r2, u32& r3, u32 addr) {
    asm volatile("ldmatrix.sync.aligned.m8n8.x4.shared.b16 {%0,%1,%2,%3}, [%4];"
                 : "=r"(r0), "=r"(r1), "=r"(r2), "=r"(r3) : "r"(addr));
}
__device__ __forceinline__ void mma16816(float* c, u32 a0, u32 a1, u32 a2, u32 a3,
                                         u32 b0, u32 b1) {
    asm volatile("mma.sync.aligned.m16n8k16.row.col.f32.f16.f16.f32 "
                 "{%0,%1,%2,%3}, {%4,%5,%6,%7}, {%8,%9}, {%0,%1,%2,%3};"
                 : "+f"(c[0]), "+f"(c[1]), "+f"(c[2]), "+f"(c[3])
                 : "r"(a0), "r"(a1), "r"(a2), "r"(a3), "r"(b0), "r"(b1));
}
__device__ __forceinline__ float ex2f(float x) {
    float r; asm("ex2.approx.f32 %0, %1;" : "=f"(r) : "f"(x)); return r;
}
__device__ __forceinline__ float lg2f(float x) {
    float r; asm("lg2.approx.f32 %0, %1;" : "=f"(r) : "f"(x)); return r;
}
__device__ __forceinline__ u32 packh(__half a, __half b) {
    __half2 hh = __halves2half2(a, b);
    return *(u32*)&hh;
}

// ---- kernel 1: prep -------------------------------------------------------
__global__ void prep(const float* __restrict__ z, const float* __restrict__ emb) {
    int tid = threadIdx.x;
    float val[C_DIM];
    __half h1[C_DIM], h2[C_DIM];

    if (blockIdx.x < 32) {
        int r = blockIdx.x * 256 + tid;
        const float4* src = (const float4*)(emb + r * C_DIM);
        float ss = 0.f;
#pragma unroll
        for (int i = 0; i < 8; i++) {
            float4 v = src[i];
            val[4 * i] = v.x; val[4 * i + 1] = v.y; val[4 * i + 2] = v.z; val[4 * i + 3] = v.w;
            ss += v.x * v.x + v.y * v.y + v.z * v.z + v.w * v.w;
        }
        float rcp = 1.0f / fmaxf(sqrtf(ss), L2EPS);
        float es = 0.f;
        float4* dst = (float4*)(g_en + r * C_DIM);
#pragma unroll
        for (int c = 0; c < C_DIM; c++) { val[c] *= rcp; es = fmaf(val[c], val[c], es); }
#pragma unroll
        for (int i = 0; i < 8; i++)
            dst[i] = make_float4(val[4 * i], val[4 * i + 1], val[4 * i + 2], val[4 * i + 3]);
        g_esq2[r] = es * L2E;
#pragma unroll
        for (int c = 0; c < C_DIM; c++) {
            h1[c] = __float2half_rn(val[c]);
            h2[c] = __float2half_rn((val[c] - __half2float(h1[c])) * RSCALE);
        }
        const __half* segs[3] = { h1, h2, h1 };       // B: e1 | e2' | e1
        u32* brow = g_bbf + (size_t)r * KK;
#pragma unroll
        for (int s = 0; s < 3; s++)
#pragma unroll
            for (int q = 0; q < 16; q++)
                brow[s * 16 + q] = packh(segs[s][2 * q], segs[s][2 * q + 1]);
    } else {
        int n = (blockIdx.x - 32) * 256 + tid;
        int b = n >> 10, hw = n & 1023;
        const float* zp = z + b * (C_DIM * 1024) + hw;
        float ss = 0.f;
#pragma unroll
        for (int c = 0; c < C_DIM; c++) { val[c] = zp[c * 1024]; ss = fmaf(val[c], val[c], ss); }
        float rcp = 1.0f / fmaxf(sqrtf(ss), L2EPS);
        float4* dst = (float4*)(g_zfn + n * C_DIM);
#pragma unroll
        for (int i = 0; i < 8; i++)
            dst[i] = make_float4(val[4 * i] * rcp, val[4 * i + 1] * rcp,
                                 val[4 * i + 2] * rcp, val[4 * i + 3] * rcp);
#pragma unroll
        for (int c = 0; c < C_DIM; c++) {
            float zs = val[c] * rcp * L2E;
            h1[c] = __float2half_rn(zs);
            h2[c] = __float2half_rn((zs - __half2float(h1[c])) * RSCALE);
        }
        const __half* segs[3] = { h1, h1, h2 };       // A: z1 | z1 | z2'
        u32* arow = g_abf + (size_t)n * KK;
#pragma unroll
        for (int s = 0; s < 3; s++)
#pragma unroll
            for (int q = 0; q < 16; q++)
                arow[s * 16 + q] = packh(segs[s][2 * q], segs[s][2 * q + 1]);
    }
}

// ---- kernel 2: HMMA similarity scan, software-pipelined --------------------
// grid (64, 2), 512 threads. warp = (rowgrp r=w&7 -> tokens, colhalf h=w>>3).
__global__ __launch_bounds__(512, 1) void vq_main() {
    extern __shared__ __align__(16) char dsm[];
    u32 sb = smem_u32(dsm);                       // [2][TILE*RSW] u32
    float* sE = (float*)(dsm + 2 * BUF_BYTES);    // [4][TILE]

    int tid = threadIdx.x;
    int w = tid >> 5, lane = tid & 31;
    int r = w & 7, h = w >> 3;
    int g = lane >> 2, tg = lane & 3;
    int Rb = blockIdx.x * TOKB + r * 16;
    int vbase = blockIdx.y * VPB;

    // A fragments: 6 k16-steps x 4 regs (rows Rb+g, Rb+g+8), loaded once.
    u32 af[6][4];
    {
        const u32* A0 = g_abf + (size_t)(Rb + g) * KK;
        const u32* A8 = g_abf + (size_t)(Rb + g + 8) * KK;
#pragma unroll
        for (int ks = 0; ks < 6; ks++) {
            af[ks][0] = A0[ks * 8 + tg];
            af[ks][1] = A8[ks * 8 + tg];
            af[ks][2] = A0[ks * 8 + tg + 4];
            af[ks][3] = A8[ks * 8 + tg + 4];
        }
    }

    u32 lm_off = (u32)((((lane >> 4) & 1) * 8 + (lane & 7)) * (RSW * 4) + ((lane >> 3) & 1) * 16);
    u32 colbase = (u32)(h * 32) * (RSW * 4);

    float accm[2][4][4], accr[2][4][4];
    float bd0 = 3.4e38f, bd1 = 3.4e38f, ss0 = 0.f, ss1 = 0.f;
    int bi0 = 0, bi1 = 0;

#define STAGE(T) do { \
    u32 _dst = sb + (u32)((T) & 1) * BUF_BYTES; \
    const char* _gs = (const char*)(g_bbf + (size_t)(vbase + (T) * TILE) * KK); \
    for (int _ch = tid; _ch < 768; _ch += 512) { \
        int _row = _ch / 12, _col = _ch % 12; \
        cpa16(_dst + (u32)(_row * (RSW * 4) + _col * 16), _gs + (size_t)_row * 192 + _col * 16); \
    } \
    if (tid < 16) cpa16(smem_u32(sE + ((T) & 3) * TILE) + (u32)tid * 16, \
                        (const char*)(g_esq2 + vbase + (T) * TILE) + tid * 16); \
    cpa_commit(); \
} while (0)

#define LOADMMA(T, SET) do { \
    cpa_wait<0>(); \
    __syncthreads(); \
    if ((T) + 1 < NTIL) STAGE((T) + 1); \
    _Pragma("unroll") \
    for (int _nb = 0; _nb < 4; _nb++) { \
        _Pragma("unroll") \
        for (int _q = 0; _q < 4; _q++) { accm[SET][_nb][_q] = 0.f; accr[SET][_nb][_q] = 0.f; } \
    } \
    u32 _bb = sb + (u32)((T) & 1) * BUF_BYTES + colbase + lm_off; \
    _Pragma("unroll") \
    for (int _ks = 0; _ks < 6; _ks++) { \
        float (*_acc)[4] = (_ks < 2) ? accm[SET] : accr[SET]; \
        _Pragma("unroll") \
        for (int _np = 0; _np < 2; _np++) { \
            u32 _b0, _b1, _b2, _b3; \
            ldm_x4(_b0, _b1, _b2, _b3, _bb + (u32)(_np * 16 * (RSW * 4) + _ks * 32)); \
            mma16816(_acc[2 * _np],     af[_ks][0], af[_ks][1], af[_ks][2], af[_ks][3], _b0, _b1); \
            mma16816(_acc[2 * _np + 1], af[_ks][0], af[_ks][1], af[_ks][2], af[_ks][3], _b2, _b3); \
        } \
    } \
} while (0)

#define EPI(T, SET) do { \
    const float* _se = sE + ((T) & 3) * TILE + h * 32 + 2 * tg; \
    int _cb = vbase + (T) * TILE + h * 32 + 2 * tg; \
    _Pragma("unroll") \
    for (int _nb = 0; _nb < 4; _nb++) { \
        float2 _e = *(const float2*)(_se + _nb * 8); \
        int _c0 = _cb + _nb * 8, _c1 = _c0 + 1; \
        float _u00 = fmaf(accr[SET][_nb][0], RINV, accm[SET][_nb][0]); \
        float _u01 = fmaf(accr[SET][_nb][1], RINV, accm[SET][_nb][1]); \
        float _u10 = fmaf(accr[SET][_nb][2], RINV, accm[SET][_nb][2]); \
        float _u11 = fmaf(accr[SET][_nb][3], RINV, accm[SET][_nb][3]); \
        float _d; \
        _d = fmaf(-2.f, _u00, _e.x); if (_d < bd0) { bd0 = _d; bi0 = _c0; } \
        _d = fmaf(-2.f, _u01, _e.y); if (_d < bd0) { bd0 = _d; bi0 = _c1; } \
        _d = fmaf(-2.f, _u10, _e.x); if (_d < bd1) { bd1 = _d; bi1 = _c0; } \
        _d = fmaf(-2.f, _u11, _e.y); if (_d < bd1) { bd1 = _d; bi1 = _c1; } \
        ss0 += ex2f(_u00) + ex2f(_u01); \
        ss1 += ex2f(_u10) + ex2f(_u11); \
    } \
} while (0)

    STAGE(0);
    LOADMMA(0, 0);
    for (int i = 0; i < NTIL; i += 2) {
        LOADMMA(i + 1, 1);
        EPI(i, 0);                       // under mma(i+1)'s tensor shadow
        if (i + 2 < NTIL) LOADMMA(i + 2, 0);
        EPI(i + 1, 1);
    }

    // reduce across the 4 threads of each row-group (quads), lexicographic
#pragma unroll
    for (int o = 1; o < 4; o <<= 1) {
        float od = __shfl_down_sync(~0u, bd0, o, 4);
        int   oi = __shfl_down_sync(~0u, bi0, o, 4);
        float os = __shfl_down_sync(~0u, ss0, o, 4);
        if (od < bd0 || (od == bd0 && oi < bi0)) { bd0 = od; bi0 = oi; }
        ss0 += os;
        od = __shfl_down_sync(~0u, bd1, o, 4);
        oi = __shfl_down_sync(~0u, bi1, o, 4);
        os = __shfl_down_sync(~0u, ss1, o, 4);
        if (od < bd1 || (od == bd1 && oi < bi1)) { bd1 = od; bi1 = oi; }
        ss1 += os;
    }
    if (tg == 0) {
        int sp = blockIdx.y * 2 + h;
        int o0 = (Rb + g) * VS + sp;
        int o1 = (Rb + g + 8) * VS + sp;
        g_pd[o0] = bd0; g_pi[o0] = bi0; g_ps[o0] = ss0;
        g_pd[o1] = bd1; g_pi[o1] = bi1; g_ps[o1] = ss1;
    }
#undef STAGE
#undef LOADMMA
#undef EPI
}

// ---- kernel 3: merge splits + losses + NCHW output -------------------------
__global__ void vq_reduce(float* __restrict__ out) {
    int n = blockIdx.x * 256 + threadIdx.x;
    float4 pd = *(const float4*)(g_pd + n * VS);
    int4   pi = *(const int4*)(g_pi + n * VS);
    float4 ps = *(const float4*)(g_ps + n * VS);

    float bd = pd.x; int bi = pi.x;
    if (pd.y < bd || (pd.y == bd && pi.y < bi)) { bd = pd.y; bi = pi.y; }
    if (pd.z < bd || (pd.z == bd && pi.z < bi)) { bd = pd.z; bi = pi.z; }
    if (pd.w < bd || (pd.w == bd && pi.w < bi)) { bd = pd.w; bi = pi.w; }
    float S = ps.x + ps.y + ps.z + ps.w;
    float lse = lg2f(S) * LN2;

    const float4* ep = (const float4*)(g_en + (size_t)bi * C_DIM);
    const float4* zp = (const float4*)(g_zfn + (size_t)n * C_DIM);
    int b = n >> 10, hw = n & 1023;
    float* op = out + b * (C_DIM * 1024) + hw;
    float dot = 0.f, vq = 0.f;
#pragma unroll
    for (int i = 0; i < 8; i++) {
        float4 e = ep[i], zt = zp[i];
        dot = fmaf(e.x, zt.x, fmaf(e.y, zt.y, fmaf(e.z, zt.z, fmaf(e.w, zt.w, dot))));
        float dx = e.x - zt.x, dy = e.y - zt.y, dz = e.z - zt.z, dw = e.w - zt.w;
        vq = fmaf(dx, dx, fmaf(dy, dy, fmaf(dz, dz, fmaf(dw, dw, vq))));
        op[(4 * i + 0) * 1024] = e.x;
        op[(4 * i + 1) * 1024] = e.y;
        op[(4 * i + 2) * 1024] = e.z;
        op[(4 * i + 3) * 1024] = e.w;
    }
    float commit = lse - dot;

    __shared__ float sred[16];
    float v1 = vq, c1 = commit;
#pragma unroll
    for (int o = 16; o; o >>= 1) {
        v1 += __shfl_down_sync(~0u, v1, o);
        c1 += __shfl_down_sync(~0u, c1, o);
    }
    int wid = threadIdx.x >> 5, lid = threadIdx.x & 31;
    if (lid == 0) { sred[wid] = v1; sred[wid + 8] = c1; }
    __syncthreads();
    if (threadIdx.x == 0) {
        float vs = 0.f, cs = 0.f;
#pragma unroll
        for (int i = 0; i < 8; i++) { vs += sred[i]; cs += sred[i + 8]; }
        g_blk[blockIdx.x][0] = vs; g_blk[blockIdx.x][1] = cs;
        __threadfence();
        if (atomicAdd(&g_cnt, 1) == 31) {
            float va = 0.f, ca = 0.f;
            for (int i = 0; i < 32; i++) { va += g_blk[i][0]; ca += g_blk[i][1]; }
            out[N_TOK * C_DIM]     = va / (float)(N_TOK * C_DIM);
            out[N_TOK * C_DIM + 1] = 0.25f * (ca / (float)N_TOK);
            g_cnt = 0;
        }
    }
}

// ---------------------------------------------------------------------------
extern "C" void kernel_launch(void* const* d_in, const int* in_sizes, int n_in,
                              void* d_out, int out_size) {
    const float* z = (const float*)d_in[0];
    const float* emb = (const float*)d_in[1];
    if (n_in >= 2 && in_sizes[0] == V_CODES * C_DIM && in_sizes[1] == N_TOK * 8) {
        const float* t = z; z = emb; emb = t;
    }
    cudaFuncSetAttribute(vq_main, cudaFuncAttributeMaxDynamicSharedMemorySize, SMEM_DYN);
    prep<<<64, 256>>>(z, emb);
    dim3 grid(N_TOK / TOKB, YS);
    vq_main<<<grid, 512, SMEM_DYN>>>();
    vq_reduce<<<N_TOK / 256, 256>>>((float*)d_out);
    (void)out_size;
}